// round 1
// baseline (speedup 1.0000x reference)
#include <cuda_runtime.h>

// CAM module: out[b] = (q[b] @ k[b]^T) @ v[b] + v[b]
// Reassociated: S[b] = k[b]^T @ v[b]  (N x N, N=49);  out[b] = q[b] @ S[b] + v[b]
// B=128, C=1024, H=W=7, N=49. fp32 throughout.

#define BB 128
#define CC 1024
#define NN 49
#define NP 50   // padded row stride in smem (conflict mitigation)

__global__ __launch_bounds__(256, 1)
void cam_kernel(const float* __restrict__ v,
                const float* __restrict__ q,
                const float* __restrict__ k,
                float* __restrict__ out) {
    __shared__ float S_sh[NN * NP];        // 2450 floats: S[i][j] = sum_c k[c][i]*v[c][j]
    __shared__ float stage[2 * 64 * NP];   // 6400 floats: k/v chunk (phase1), q chunk (phase2)

    const int b   = blockIdx.x;
    const int tid = threadIdx.x;
    const float* kb = k + (size_t)b * CC * NN;
    const float* vb = v + (size_t)b * CC * NN;
    const float* qb = q + (size_t)b * CC * NN;
    float*       ob = out + (size_t)b * CC * NN;

    // ---- zero S accumulator ----
    for (int idx = tid; idx < NN * NP; idx += 256) S_sh[idx] = 0.f;

    // ================= Phase 1: S = k^T @ v  =================
    // 4 groups x 49 threads; each thread owns a 7x7 tile of S,
    // each group accumulates over its 16-channel slice of each 64-ch chunk.
    const int g  = tid / 49;          // 0..5, active when g < 4
    const int t  = tid % 49;
    const int ti = (t / 7) * 7;       // S row base (k's n index)
    const int tj = (t % 7) * 7;       // S col base (v's n index)

    float acc[7][7];
    #pragma unroll
    for (int a = 0; a < 7; a++)
        #pragma unroll
        for (int d = 0; d < 7; d++) acc[a][d] = 0.f;

    float* k_sh = stage;              // [64][NP]
    float* v_sh = stage + 64 * NP;    // [64][NP]

    for (int c0 = 0; c0 < CC; c0 += 64) {
        __syncthreads();
        // cooperative coalesced load of 64 channels of k and v
        for (int idx = tid; idx < 64 * NN; idx += 256) {
            int cc = idx / NN, ii = idx % NN;
            k_sh[cc * NP + ii] = kb[(size_t)(c0 + cc) * NN + ii];
            v_sh[cc * NP + ii] = vb[(size_t)(c0 + cc) * NN + ii];
        }
        __syncthreads();
        if (g < 4) {
            #pragma unroll 4
            for (int cl = 0; cl < 16; cl++) {
                const int cc = g * 16 + cl;
                float kr[7], vr[7];
                #pragma unroll
                for (int a = 0; a < 7; a++) kr[a] = k_sh[cc * NP + ti + a];
                #pragma unroll
                for (int d = 0; d < 7; d++) vr[d] = v_sh[cc * NP + tj + d];
                #pragma unroll
                for (int a = 0; a < 7; a++)
                    #pragma unroll
                    for (int d = 0; d < 7; d++)
                        acc[a][d] += kr[a] * vr[d];
            }
        }
    }
    __syncthreads();
    if (g < 4) {
        #pragma unroll
        for (int a = 0; a < 7; a++)
            #pragma unroll
            for (int d = 0; d < 7; d++)
                atomicAdd(&S_sh[(ti + a) * NP + tj + d], acc[a][d]);
    }
    __syncthreads();

    // ================= Phase 2: out = q @ S + v =================
    // 224 active threads: 32 channel-groups (4 ch each) x 7 j-tiles (7 cols each).
    const int cg = tid / 7;           // 0..36, active when cg < 32
    const int jt = (tid % 7) * 7;     // output col base
    float* q_sh = stage;              // [128][NP] = 6400 floats (fits staging)

    for (int c0 = 0; c0 < CC; c0 += 128) {
        __syncthreads();
        for (int idx = tid; idx < 128 * NN; idx += 256) {
            int cc = idx / NN, ii = idx % NN;
            q_sh[cc * NP + ii] = qb[(size_t)(c0 + cc) * NN + ii];
        }
        __syncthreads();
        if (cg < 32) {
            const int cbase = cg * 4;
            float o[4][7];
            #pragma unroll
            for (int a = 0; a < 4; a++)
                #pragma unroll
                for (int d = 0; d < 7; d++) o[a][d] = 0.f;

            #pragma unroll 7
            for (int i = 0; i < NN; i++) {
                float qv[4], sv[7];
                #pragma unroll
                for (int a = 0; a < 4; a++) qv[a] = q_sh[(cbase + a) * NP + i];
                #pragma unroll
                for (int d = 0; d < 7; d++) sv[d] = S_sh[i * NP + jt + d];
                #pragma unroll
                for (int a = 0; a < 4; a++)
                    #pragma unroll
                    for (int d = 0; d < 7; d++)
                        o[a][d] += qv[a] * sv[d];
            }
            #pragma unroll
            for (int a = 0; a < 4; a++) {
                const size_t crow = (size_t)(c0 + cbase + a) * NN;
                #pragma unroll
                for (int d = 0; d < 7; d++) {
                    const int j = jt + d;
                    ob[crow + j] = o[a][d] + vb[crow + j];
                }
            }
        }
    }
}

extern "C" void kernel_launch(void* const* d_in, const int* in_sizes, int n_in,
                              void* d_out, int out_size) {
    const float* v1 = (const float*)d_in[0];
    const float* q1 = (const float*)d_in[1];
    const float* k1 = (const float*)d_in[2];
    float* out = (float*)d_out;
    cam_kernel<<<BB, 256>>>(v1, q1, k1, out);
}

// round 3
// speedup vs baseline: 1.4394x; 1.4394x over previous
#include <cuda_runtime.h>

// CAM: out[b] = (q[b] @ k[b]^T) @ v[b] + v[b]
// Reassociated: S[b] = k[b]^T @ v[b] (49x49); out[b] = q[b] @ S[b] + v[b]
// B=128, C=1024, N=49 (7x7), fp32.
//
// Two-kernel split for parallelism:
//   A: grid (128,8) — partial S over 128-channel slices -> SP_glob
//      (staged as 2 x 64-channel sub-chunks to stay under 48KB static smem)
//   B: grid (128,8) — reduce partials, out-slice = q_slice @ S + v_slice

#define BB 128
#define CC 1024
#define NN 49
#define PP 8            // channel splits
#define CH 128          // channels per block (CC/PP)
#define SC 64           // staging sub-chunk channels

__device__ float SP_glob[BB * PP * NN * NN];   // 9.83 MB partial-S scratch

// ---------------- Kernel A: partial S = k_slice^T @ v_slice ----------------
__global__ __launch_bounds__(256)
void cam_partS(const float* __restrict__ k, const float* __restrict__ v) {
    __shared__ float k_sh[SC * NN];   // 12.25 KB
    __shared__ float v_sh[SC * NN];   // 12.25 KB
    __shared__ float S_sh[NN * NN];   // 9.4 KB   -> total ~34 KB

    const int b = blockIdx.x;
    const int p = blockIdx.y;
    const int tid = threadIdx.x;
    const size_t base = ((size_t)b * CC + (size_t)p * CH) * NN;

    for (int idx = tid; idx < NN * NN; idx += 256) S_sh[idx] = 0.f;

    // 4 groups x 49 threads; each thread owns a 7x7 tile of S,
    // each group covers 16 channels of each 64-channel sub-chunk.
    const int g = tid / 49;           // active when g < 4
    const int t = tid % 49;
    const int ti = (t / 7) * 7;
    const int tj = (t % 7) * 7;

    float acc[7][7];
    #pragma unroll
    for (int a = 0; a < 7; a++)
        #pragma unroll
        for (int d = 0; d < 7; d++) acc[a][d] = 0.f;

    #pragma unroll
    for (int chunk = 0; chunk < CH / SC; chunk++) {
        __syncthreads();
        // vectorized staging of 64 channels of k and v: 3136 floats = 784 float4
        const float4* k4 = (const float4*)(k + base + (size_t)chunk * SC * NN);
        const float4* v4 = (const float4*)(v + base + (size_t)chunk * SC * NN);
        for (int idx = tid; idx < (SC * NN) / 4; idx += 256) {
            ((float4*)k_sh)[idx] = k4[idx];
            ((float4*)v_sh)[idx] = v4[idx];
        }
        __syncthreads();

        if (g < 4) {
            #pragma unroll 4
            for (int cl = 0; cl < 16; cl++) {
                const int cc = g * 16 + cl;
                float kr[7], vr[7];
                #pragma unroll
                for (int a = 0; a < 7; a++) kr[a] = k_sh[cc * NN + ti + a];
                #pragma unroll
                for (int d = 0; d < 7; d++) vr[d] = v_sh[cc * NN + tj + d];
                #pragma unroll
                for (int a = 0; a < 7; a++)
                    #pragma unroll
                    for (int d = 0; d < 7; d++)
                        acc[a][d] += kr[a] * vr[d];
            }
        }
    }

    if (g < 4) {
        #pragma unroll
        for (int a = 0; a < 7; a++)
            #pragma unroll
            for (int d = 0; d < 7; d++)
                atomicAdd(&S_sh[(ti + a) * NN + tj + d], acc[a][d]);
    }
    __syncthreads();

    float* sp = SP_glob + (size_t)(b * PP + p) * NN * NN;
    for (int idx = tid; idx < NN * NN; idx += 256) sp[idx] = S_sh[idx];
}

// ---------------- Kernel B: out_slice = q_slice @ S + v_slice ----------------
__global__ __launch_bounds__(256)
void cam_out(const float* __restrict__ q, const float* __restrict__ v,
             float* __restrict__ out) {
    __shared__ float q_sh[CH * NN];   // 25.1 KB
    __shared__ float S_sh[NN * NN];   // 9.4 KB  -> total ~34.5 KB

    const int b = blockIdx.x;
    const int p = blockIdx.y;
    const int tid = threadIdx.x;
    const size_t base = ((size_t)b * CC + (size_t)p * CH) * NN;

    // reduce the 8 partial S matrices (L2-resident)
    const float* sp0 = SP_glob + (size_t)b * PP * NN * NN;
    for (int idx = tid; idx < NN * NN; idx += 256) {
        float s = 0.f;
        #pragma unroll
        for (int pp = 0; pp < PP; pp++) s += sp0[pp * NN * NN + idx];
        S_sh[idx] = s;
    }

    // stage q slice: 6272 floats = 1568 float4
    const float4* q4 = (const float4*)(q + base);
    for (int idx = tid; idx < (CH * NN) / 4; idx += 256)
        ((float4*)q_sh)[idx] = q4[idx];
    __syncthreads();

    // 32 channel-groups (4 ch each) x 7 col-tiles (7 cols each) = 224 threads
    const int cg = tid / 7;           // active when cg < 32
    const int jt = (tid % 7) * 7;

    if (cg < 32) {
        const int cbase = cg * 4;
        float o[4][7];
        #pragma unroll
        for (int a = 0; a < 4; a++)
            #pragma unroll
            for (int d = 0; d < 7; d++) o[a][d] = 0.f;

        #pragma unroll 7
        for (int i = 0; i < NN; i++) {
            float qv[4], sv[7];
            #pragma unroll
            for (int a = 0; a < 4; a++) qv[a] = q_sh[(cbase + a) * NN + i];
            #pragma unroll
            for (int d = 0; d < 7; d++) sv[d] = S_sh[i * NN + jt + d];
            #pragma unroll
            for (int a = 0; a < 4; a++)
                #pragma unroll
                for (int d = 0; d < 7; d++)
                    o[a][d] += qv[a] * sv[d];
        }

        const float* vb = v + base;
        float* ob = out + base;
        #pragma unroll
        for (int a = 0; a < 4; a++) {
            const int crow = (cbase + a) * NN;
            #pragma unroll
            for (int d = 0; d < 7; d++) {
                const int j = jt + d;
                ob[crow + j] = o[a][d] + vb[crow + j];
            }
        }
    }
}

extern "C" void kernel_launch(void* const* d_in, const int* in_sizes, int n_in,
                              void* d_out, int out_size) {
    const float* v1 = (const float*)d_in[0];
    const float* q1 = (const float*)d_in[1];
    const float* k1 = (const float*)d_in[2];
    float* out = (float*)d_out;

    dim3 grid(BB, PP);
    cam_partS<<<grid, 256>>>(k1, v1);
    cam_out<<<grid, 256>>>(q1, v1, out);
}